// round 1
// baseline (speedup 1.0000x reference)
#include <cuda_runtime.h>
#include <math_constants.h>

#define N_ROWS  128
#define IN_DIM  1024
#define OUT_DIM 1024

#define TM 32          // n-tile per block
#define TN 32          // o-tile per block
#define KC 64          // k-chunk in smem
#define PAD 4
#define LDSTR (KC + PAD)   // 68 floats: 16B-aligned rows, conflict-benign banks

__global__ __launch_bounds__(128, 1)
void tropical_linear_kernel(const float* __restrict__ x,
                            const float* __restrict__ w,
                            const float* __restrict__ bias,
                            float* __restrict__ out) {
    __shared__ float xs[TM * LDSTR];
    __shared__ float ws[TN * LDSTR];

    const int tx  = threadIdx.x;          // 0..15 -> o direction
    const int ty  = threadIdx.y;          // 0..7  -> n direction
    const int tid = ty * 16 + tx;
    const int n0  = blockIdx.y * TM;
    const int o0  = blockIdx.x * TN;

    float acc[4][2];
    #pragma unroll
    for (int i = 0; i < 4; i++)
        #pragma unroll
        for (int j = 0; j < 2; j++)
            acc[i][j] = -CUDART_INF_F;

    for (int k0 = 0; k0 < IN_DIM; k0 += KC) {
        // Load x tile [TM x KC] and w tile [TN x KC]: 2048 floats each = 512 float4.
        // 128 threads x 4 float4 per array. Coalesced along k.
        #pragma unroll
        for (int i = 0; i < 4; i++) {
            int f   = tid + i * 128;        // 0..511
            int row = f >> 4;               // KC/4 = 16 float4 per row
            int c4  = f & 15;
            float4 vx = *(const float4*)&x[(n0 + row) * IN_DIM + k0 + c4 * 4];
            *(float4*)&xs[row * LDSTR + c4 * 4] = vx;
            float4 vw = *(const float4*)&w[(o0 + row) * IN_DIM + k0 + c4 * 4];
            *(float4*)&ws[row * LDSTR + c4 * 4] = vw;
        }
        __syncthreads();

        #pragma unroll
        for (int kk = 0; kk < KC; kk += 4) {
            float4 xv[4];
            float4 wv[2];
            #pragma unroll
            for (int i = 0; i < 4; i++)
                xv[i] = *(const float4*)&xs[(ty * 4 + i) * LDSTR + kk];
            #pragma unroll
            for (int j = 0; j < 2; j++)
                wv[j] = *(const float4*)&ws[(tx * 2 + j) * LDSTR + kk];

            #pragma unroll
            for (int i = 0; i < 4; i++)
                #pragma unroll
                for (int j = 0; j < 2; j++) {
                    acc[i][j] = fmaxf(acc[i][j], xv[i].x + wv[j].x);
                    acc[i][j] = fmaxf(acc[i][j], xv[i].y + wv[j].y);
                    acc[i][j] = fmaxf(acc[i][j], xv[i].z + wv[j].z);
                    acc[i][j] = fmaxf(acc[i][j], xv[i].w + wv[j].w);
                }
        }
        __syncthreads();
    }

    #pragma unroll
    for (int i = 0; i < 4; i++) {
        int n = n0 + ty * 4 + i;
        #pragma unroll
        for (int j = 0; j < 2; j++) {
            int o = o0 + tx * 2 + j;
            out[n * OUT_DIM + o] = acc[i][j] + bias[o];
        }
    }
}

extern "C" void kernel_launch(void* const* d_in, const int* in_sizes, int n_in,
                              void* d_out, int out_size) {
    const float* x    = (const float*)d_in[0];   // [128, 1024]
    const float* wgt  = (const float*)d_in[1];   // [1024, 1024]
    const float* bias = (const float*)d_in[2];   // [1024]
    float* out        = (float*)d_out;           // [128, 1024]

    dim3 grid(OUT_DIM / TN, N_ROWS / TM);        // (32, 4) = 128 blocks
    dim3 block(16, 8);                           // 128 threads
    tropical_linear_kernel<<<grid, block>>>(x, wgt, bias, out);
}